// round 5
// baseline (speedup 1.0000x reference)
#include <cuda_runtime.h>
#include <cuda_bf16.h>
#include <math.h>
#include <stdint.h>

// SwitchGate fused, mma.sync edition with fragment-layout weights.
// logits = X @ W^T + b via split-bf16 3-pass MMA (Ah*Bh + Ah*Bl + Al*Bh, fp32 acc)
// then softmax(E=64) -> top2 -> batch denominator -> *capacity(5).
//
// X[4][4096][4096] f32, W[64][4096] f32, b[64] f32, out[4][4096][64] f32.
// Block: 32 s x 4 b = M=128 rows, N=64 experts. grid=128.
// 8 warps = 4 m-positions x 2 n-halves; each warp: 2 m16 strips x n32.
// W pre-packed in per-lane MMA fragment order -> B via coalesced LDG.128 only.

#define B_DIM 4
#define S_DIM 4096
#define D_DIM 4096
#define E_DIM 64

#define TS 32
#define MROWS 128
#define KC 64
#define NCHUNK 64
#define NTHREADS 256
#define LSTR 65

#define AH_OFF 0
#define AL_OFF 16384
#define BUF_BYTES 32768
#define DYN_BYTES (2 * BUF_BYTES + 1024)

#define SWZ(b) ((b) ^ (((b) >> 3) & 0x70))

// W fragments: [t = ch*4+ks][nt 0..7][lane 0..31] -> uint4{bh0,bh1,bl0,bl1}
__device__ uint4 g_Wfrag[NCHUNK * 4 * 8 * 32];

// Truncation split: hi = top 16 bits (exact bf16), lo = bf16_rn(f - hi).
__device__ __forceinline__ void split_pack(float f0, float f1,
                                           uint32_t& hp, uint32_t& lp) {
    uint32_t u0 = __float_as_uint(f0), u1 = __float_as_uint(f1);
    asm("prmt.b32 %0, %1, %2, 0x7632;" : "=r"(hp) : "r"(u0), "r"(u1));
    float h0 = __uint_as_float(u0 & 0xFFFF0000u);
    float h1 = __uint_as_float(u1 & 0xFFFF0000u);
    float l0 = f0 - h0, l1 = f1 - h1;
    asm("cvt.rn.bf16x2.f32 %0, %1, %2;" : "=r"(lp) : "f"(l1), "f"(l0));
}

// Pack W into MMA B-fragment lane order.
// m16n8k16 B frag: thread(lane) holds B[k=(lane&3)*2 + {0,1} (+8)][n=lane>>2]
// with W row-major [e=n][k]: b0 = W[n][kb..kb+1], b1 = W[n][kb+8..kb+9].
__global__ void wfrag_kernel(const float* __restrict__ W) {
    int i = blockIdx.x * blockDim.x + threadIdx.x;
    if (i >= NCHUNK * 4 * 8 * 32) return;
    int lane = i & 31;
    int nt   = (i >> 5) & 7;
    int t    = i >> 8;                  // ch*4 + ks
    int e    = nt * 8 + (lane >> 2);
    int kb   = t * 16 + (lane & 3) * 2;
    const float* row = W + (size_t)e * D_DIM;
    float w0 = row[kb],     w1 = row[kb + 1];
    float w2 = row[kb + 8], w3 = row[kb + 9];
    uint32_t bh0, bl0, bh1, bl1;
    split_pack(w0, w1, bh0, bl0);
    split_pack(w2, w3, bh1, bl1);
    g_Wfrag[i] = make_uint4(bh0, bh1, bl0, bl1);
}

__device__ __forceinline__ uint32_t smem_u32(const void* p) {
    uint32_t a;
    asm("{ .reg .u64 t; cvta.to.shared.u64 t, %1; cvt.u32.u64 %0, t; }" : "=r"(a) : "l"(p));
    return a;
}
__device__ __forceinline__ void ldm_x4(uint32_t& r0, uint32_t& r1, uint32_t& r2,
                                       uint32_t& r3, uint32_t addr) {
    asm volatile("ldmatrix.sync.aligned.m8n8.x4.shared.b16 {%0,%1,%2,%3}, [%4];\n"
                 : "=r"(r0), "=r"(r1), "=r"(r2), "=r"(r3)
                 : "r"(addr));
}
__device__ __forceinline__ void mma_bf16(float* c, const uint32_t* a,
                                         uint32_t b0, uint32_t b1) {
    asm volatile(
        "mma.sync.aligned.m16n8k16.row.col.f32.bf16.bf16.f32 "
        "{%0,%1,%2,%3}, {%4,%5,%6,%7}, {%8,%9}, {%0,%1,%2,%3};\n"
        : "+f"(c[0]), "+f"(c[1]), "+f"(c[2]), "+f"(c[3])
        : "r"(a[0]), "r"(a[1]), "r"(a[2]), "r"(a[3]), "r"(b0), "r"(b1));
}

__global__ __launch_bounds__(NTHREADS, 1)
void switch_gate_mma2(const float* __restrict__ X,
                      const float* __restrict__ bias,
                      float* __restrict__ out)
{
    extern __shared__ unsigned char dyn[];
    __shared__ float sBias[E_DIM];
    __shared__ float sP1[MROWS], sP2[MROWS];
    __shared__ int   sI1[MROWS], sI2[MROWS];

    const int tid  = threadIdx.x;
    const int lane = tid & 31;
    const int wid  = tid >> 5;
    const int mg   = wid >> 1;   // 0..3
    const int nh   = wid & 1;    // n-half
    const int s0   = blockIdx.x * TS;

    const uint32_t dynb  = smem_u32(dyn);
    const uint32_t sbase = (dynb + 1023u) & ~1023u;
    unsigned char* bufp  = dyn + (sbase - dynb);

    if (tid < E_DIM) sBias[tid] = bias[tid];

    // ---- X staging indices: 8 float4/thread covering 128 rows x 64 k ----
    const int xrow = tid >> 4;   // + 16*i
    const int xkq  = tid & 15;
    float4 xv[8];

    auto loadX = [&](int k0) {
        #pragma unroll
        for (int i = 0; i < 8; i++) {
            int row = xrow + 16 * i;          // row = si*4 + b
            int b = row & 3, si = row >> 2;
            xv[i] = *reinterpret_cast<const float4*>(
                &X[((size_t)(b * S_DIM + s0 + si)) * D_DIM + k0 + xkq * 4]);
        }
    };
    auto stageX = [&](unsigned char* buf) {
        #pragma unroll
        for (int i = 0; i < 8; i++) {
            int row = xrow + 16 * i;
            float4 v = xv[i];
            uint32_t hp0, lp0, hp1, lp1;
            split_pack(v.x, v.y, hp0, lp0);
            split_pack(v.z, v.w, hp1, lp1);
            uint32_t sw = SWZ((uint32_t)(row * 128 + xkq * 8));
            *reinterpret_cast<uint2*>(buf + AH_OFF + sw) = make_uint2(hp0, hp1);
            *reinterpret_cast<uint2*>(buf + AL_OFF + sw) = make_uint2(lp0, lp1);
        }
    };

    // ---- A ldmatrix lane addressing (un-swizzled bases, per strip) ----
    const int mat = lane >> 3;
    const int ar  = (mat & 1) * 8 + (lane & 7);
    const int akb = (mat >> 1) * 16;
    const uint32_t unswzA0 = (uint32_t)((mg * 16 + ar) * 128 + akb);
    const uint32_t unswzA1 = (uint32_t)((mg * 16 + 64 + ar) * 128 + akb);

    // ---- accumulators: 2 strips x 4 n-tiles x 4 ----
    float c0[4][4], c1[4][4];
    #pragma unroll
    for (int nt = 0; nt < 4; nt++)
        #pragma unroll
        for (int u = 0; u < 4; u++) { c0[nt][u] = 0.0f; c1[nt][u] = 0.0f; }

    // ---- B fragment double set ----
    uint4 bset[2][4];
    auto loadB = [&](int set, int t) {
        const uint4* bp = g_Wfrag + ((size_t)t * 256 + nh * 128 + lane);
        #pragma unroll
        for (int nt = 0; nt < 4; nt++) bset[set][nt] = bp[nt * 32];
    };

    // ---- prologue ----
    loadX(0);
    stageX(bufp);
    loadX(KC);
    loadB(0, 0);
    __syncthreads();

    for (int ch = 0; ch < NCHUNK; ch++) {
        const uint32_t bufAddr = sbase + (uint32_t)(ch & 1) * BUF_BYTES;

        #pragma unroll
        for (int ks = 0; ks < 4; ks++) {
            const int t = ch * 4 + ks;
            loadB((ks + 1) & 1, (t + 1) & (NCHUNK * 4 - 1));  // prefetch next

            const uint32_t v0 = unswzA0 + ks * 32;
            const uint32_t v1 = unswzA1 + ks * 32;
            uint32_t ah0[4], al0[4], ah1[4], al1[4];
            ldm_x4(ah0[0], ah0[1], ah0[2], ah0[3], bufAddr + AH_OFF + SWZ(v0));
            ldm_x4(al0[0], al0[1], al0[2], al0[3], bufAddr + AL_OFF + SWZ(v0));
            ldm_x4(ah1[0], ah1[1], ah1[2], ah1[3], bufAddr + AH_OFF + SWZ(v1));
            ldm_x4(al1[0], al1[1], al1[2], al1[3], bufAddr + AL_OFF + SWZ(v1));

            #pragma unroll
            for (int nt = 0; nt < 4; nt++) {
                const uint4 bb = bset[ks & 1][nt];
                mma_bf16(c0[nt], ah0, bb.x, bb.y);   // hi*hi
                mma_bf16(c0[nt], ah0, bb.z, bb.w);   // hi*lo
                mma_bf16(c0[nt], al0, bb.x, bb.y);   // lo*hi
                mma_bf16(c1[nt], ah1, bb.x, bb.y);
                mma_bf16(c1[nt], ah1, bb.z, bb.w);
                mma_bf16(c1[nt], al1, bb.x, bb.y);
            }
        }

        if (ch + 1 < NCHUNK) {
            __syncthreads();                    // buf[1-(ch&1)] free (ch-1 done)
            stageX(bufp + ((ch + 1) & 1) * BUF_BYTES);   // regs hold chunk ch+1
            if (ch + 2 < NCHUNK) loadX((ch + 2) * KC);
            __syncthreads();
        }
    }

    __syncthreads();   // all MMAs done before overlaying logits on buffers

    // ---- accumulators -> smem logits ----
    float* sLog = reinterpret_cast<float*>(bufp);
    {
        const int rq = lane >> 2;
        const int cq = (lane & 3) * 2;
        #pragma unroll
        for (int s = 0; s < 2; s++) {
            const int rbase = mg * 16 + s * 64 + rq;
            #pragma unroll
            for (int nt = 0; nt < 4; nt++) {
                const int cc = nh * 32 + nt * 8 + cq;
                const float* c = s ? c1[nt] : c0[nt];
                sLog[rbase * LSTR + cc]           = c[0];
                sLog[rbase * LSTR + cc + 1]       = c[1];
                sLog[(rbase + 8) * LSTR + cc]     = c[2];
                sLog[(rbase + 8) * LSTR + cc + 1] = c[3];
            }
        }
    }
    __syncthreads();

    // ---- per-row softmax + top-2 (strict '>' keeps lower index on ties) ----
    if (tid < MROWS) {
        const int row = tid;
        float m = -INFINITY;
        #pragma unroll
        for (int e = 0; e < E_DIM; e++)
            m = fmaxf(m, sLog[row * LSTR + e] + sBias[e]);
        float sum = 0.0f, v1 = -INFINITY, v2 = -INFINITY;
        int i1 = 0, i2 = 0;
        #pragma unroll
        for (int e = 0; e < E_DIM; e++) {
            float l = sLog[row * LSTR + e] + sBias[e];
            sum += expf(l - m);
            if (l > v1)      { v2 = v1; i2 = i1; v1 = l; i1 = e; }
            else if (l > v2) { v2 = l;  i2 = e; }
        }
        float inv = 1.0f / sum;
        sP1[row] = expf(v1 - m) * inv;
        sP2[row] = expf(v2 - m) * inv;
        sI1[row] = i1;
        sI2[row] = i2;
    }
    __syncthreads();

    // ---- batch denominator + scaled coalesced write (32 si x 64 e) ----
    #pragma unroll
    for (int i = 0; i < 8; i++) {
        int id = tid + NTHREADS * i;
        int e  = id & 63;
        int si = id >> 6;
        float val[B_DIM];
        float den = 1e-6f;
        #pragma unroll
        for (int b = 0; b < B_DIM; b++) {
            int row = si * 4 + b;
            float v = 0.0f;
            if (e == sI1[row]) v = sP1[row];
            else if (e == sI2[row]) v = sP2[row];
            val[b] = v;
            den += v;
        }
        float scale = 5.0f / den;   // capacity = int(1.25 * 4) = 5
        #pragma unroll
        for (int b = 0; b < B_DIM; b++)
            out[((size_t)(b * S_DIM + s0 + si)) * E_DIM + e] = val[b] * scale;
    }
}

extern "C" void kernel_launch(void* const* d_in, const int* in_sizes, int n_in,
                              void* d_out, int out_size)
{
    const float* X    = (const float*)d_in[0];
    const float* W    = (const float*)d_in[1];
    const float* bias = (const float*)d_in[2];
    float* out        = (float*)d_out;

    cudaFuncSetAttribute(switch_gate_mma2,
                         cudaFuncAttributeMaxDynamicSharedMemorySize, DYN_BYTES);

    wfrag_kernel<<<(NCHUNK * 4 * 8 * 32) / 256, 256>>>(W);
    switch_gate_mma2<<<S_DIM / TS, NTHREADS, DYN_BYTES>>>(X, bias, out);
}